// round 1
// baseline (speedup 1.0000x reference)
#include <cuda_runtime.h>
#include <cuda_bf16.h>
#include <math.h>

#define Bz 2
#define Sz 2048
#define Hz 1024
#define NHz 16
#define HDz 64
#define BIAS_DIM 2049

// ---------------- scratch (device globals; no allocation) ----------------
__device__ float g_pe[Sz * Hz];          // 8 MB
__device__ float g_x[Bz * Sz * Hz];      // 16 MB
__device__ float g_q[Bz * Sz * Hz];
__device__ float g_k[Bz * Sz * Hz];
__device__ float g_v[Bz * Sz * Hz];
__device__ float g_ctx[Bz * Sz * Hz];
__device__ float g_ta[Bz * Sz * 2 * Hz]; // 32 MB
__device__ float g_tb[Bz * Sz * 2 * Hz]; // 32 MB

// ---------------- PE kernel: pe = LN(pos * pe_w + pe_b) ----------------
__global__ __launch_bounds__(256) void pe_kernel(
    const float* __restrict__ pw, const float* __restrict__ pb,
    const float* __restrict__ g, const float* __restrict__ be,
    float* __restrict__ out)
{
    __shared__ float buf[Hz];
    __shared__ float red[8], red2[8];
    __shared__ float s_mean, s_rstd;
    int srow = blockIdx.x;
    int tid = threadIdx.x;
    float pos = ((float)srow - 1024.0f) / (1024.0f + 1e-6f);
    float s = 0.f, ss = 0.f;
    for (int j = tid; j < Hz; j += 256) {
        float v = pos * pw[j] + pb[j];
        buf[j] = v;
        s += v; ss += v * v;
    }
    #pragma unroll
    for (int o = 16; o > 0; o >>= 1) {
        s  += __shfl_down_sync(0xffffffffu, s, o);
        ss += __shfl_down_sync(0xffffffffu, ss, o);
    }
    if ((tid & 31) == 0) { red[tid >> 5] = s; red2[tid >> 5] = ss; }
    __syncthreads();
    if (tid == 0) {
        float S = 0.f, SS = 0.f;
        #pragma unroll
        for (int i = 0; i < 8; i++) { S += red[i]; SS += red2[i]; }
        float mean = S / Hz;
        float var = SS / Hz - mean * mean;
        s_mean = mean;
        s_rstd = rsqrtf(var + 1e-5f);
    }
    __syncthreads();
    float mean = s_mean, rstd = s_rstd;
    float* op = out + (size_t)srow * Hz;
    for (int j = tid; j < Hz; j += 256)
        op[j] = (buf[j] - mean) * rstd * g[j] + be[j];
}

// ---------------- x kernel: x = LN(hidden + pe) ----------------
__global__ __launch_bounds__(256) void x_kernel(
    const float* __restrict__ hidden, const float* __restrict__ pe,
    const float* __restrict__ g, const float* __restrict__ be,
    float* __restrict__ out)
{
    __shared__ float buf[Hz];
    __shared__ float red[8], red2[8];
    __shared__ float s_mean, s_rstd;
    int row = blockIdx.x;           // b*S + s
    int srow = row & (Sz - 1);
    int tid = threadIdx.x;
    const float* hp = hidden + (size_t)row * Hz;
    const float* pp = pe + (size_t)srow * Hz;
    float s = 0.f, ss = 0.f;
    for (int j = tid; j < Hz; j += 256) {
        float v = hp[j] + pp[j];
        buf[j] = v;
        s += v; ss += v * v;
    }
    #pragma unroll
    for (int o = 16; o > 0; o >>= 1) {
        s  += __shfl_down_sync(0xffffffffu, s, o);
        ss += __shfl_down_sync(0xffffffffu, ss, o);
    }
    if ((tid & 31) == 0) { red[tid >> 5] = s; red2[tid >> 5] = ss; }
    __syncthreads();
    if (tid == 0) {
        float S = 0.f, SS = 0.f;
        #pragma unroll
        for (int i = 0; i < 8; i++) { S += red[i]; SS += red2[i]; }
        float mean = S / Hz;
        float var = SS / Hz - mean * mean;
        s_mean = mean;
        s_rstd = rsqrtf(var + 1e-5f);
    }
    __syncthreads();
    float mean = s_mean, rstd = s_rstd;
    float* op = out + (size_t)row * Hz;
    for (int j = tid; j < Hz; j += 256)
        op[j] = (buf[j] - mean) * rstd * g[j] + be[j];
}

// ---------------- LN (+optional ReLU) over rows of length N ----------------
__global__ __launch_bounds__(256) void ln_kernel(
    const float* __restrict__ in, float* __restrict__ out,
    const float* __restrict__ g, const float* __restrict__ be,
    int N, int relu)
{
    __shared__ float buf[2 * Hz];
    __shared__ float red[8], red2[8];
    __shared__ float s_mean, s_rstd;
    int row = blockIdx.x;
    int tid = threadIdx.x;
    const float* ip = in + (size_t)row * N;
    float s = 0.f, ss = 0.f;
    for (int j = tid; j < N; j += 256) {
        float v = ip[j];
        buf[j] = v;
        s += v; ss += v * v;
    }
    #pragma unroll
    for (int o = 16; o > 0; o >>= 1) {
        s  += __shfl_down_sync(0xffffffffu, s, o);
        ss += __shfl_down_sync(0xffffffffu, ss, o);
    }
    if ((tid & 31) == 0) { red[tid >> 5] = s; red2[tid >> 5] = ss; }
    __syncthreads();
    if (tid == 0) {
        float S = 0.f, SS = 0.f;
        #pragma unroll
        for (int i = 0; i < 8; i++) { S += red[i]; SS += red2[i]; }
        float mean = S / N;
        float var = SS / N - mean * mean;
        s_mean = mean;
        s_rstd = rsqrtf(var + 1e-5f);
    }
    __syncthreads();
    float mean = s_mean, rstd = s_rstd;
    float* op = out + (size_t)row * N;
    for (int j = tid; j < N; j += 256) {
        float v = (buf[j] - mean) * rstd * g[j] + be[j];
        if (relu) v = fmaxf(v, 0.f);
        op[j] = v;
    }
}

// ---------------- SGEMM: C[M,N] = A[M,K] @ B[K,N] + bias ----------------
// BM=BN=128, BK=8, 256 threads, 8x8 micro-tile (2x 4-wide halves).
__global__ __launch_bounds__(256) void sgemm128(
    const float* __restrict__ A, const float* __restrict__ Bm,
    const float* __restrict__ bias, float* __restrict__ C,
    int M, int N, int K)
{
    __shared__ float As[8][128];
    __shared__ float Bs[8][128];
    const int bx = blockIdx.x;   // N tile
    const int by = blockIdx.y;   // M tile
    const int tid = threadIdx.x;
    const int tx = tid & 15;
    const int ty = tid >> 4;

    float acc[8][8];
    #pragma unroll
    for (int i = 0; i < 8; i++)
        #pragma unroll
        for (int j = 0; j < 8; j++) acc[i][j] = 0.f;

    const float* Ab = A + (size_t)by * 128 * K;
    const float* Bb = Bm + (size_t)bx * 128;

    const int arow = tid >> 1;
    const int acol = (tid & 1) << 2;
    const int brow = tid >> 5;
    const int bcol = (tid & 31) << 2;

    for (int kt = 0; kt < K; kt += 8) {
        float4 a4 = *(const float4*)(Ab + (size_t)arow * K + kt + acol);
        As[acol + 0][arow] = a4.x;
        As[acol + 1][arow] = a4.y;
        As[acol + 2][arow] = a4.z;
        As[acol + 3][arow] = a4.w;
        *(float4*)(&Bs[brow][bcol]) = *(const float4*)(Bb + (size_t)(kt + brow) * N + bcol);
        __syncthreads();
        #pragma unroll
        for (int k = 0; k < 8; k++) {
            float ar[8], br[8];
            *(float4*)(ar)     = *(const float4*)(&As[k][ty * 4]);
            *(float4*)(ar + 4) = *(const float4*)(&As[k][64 + ty * 4]);
            *(float4*)(br)     = *(const float4*)(&Bs[k][tx * 4]);
            *(float4*)(br + 4) = *(const float4*)(&Bs[k][64 + tx * 4]);
            #pragma unroll
            for (int i = 0; i < 8; i++)
                #pragma unroll
                for (int j = 0; j < 8; j++)
                    acc[i][j] += ar[i] * br[j];
        }
        __syncthreads();
    }

    #pragma unroll
    for (int hi = 0; hi < 2; hi++) {
        #pragma unroll
        for (int ii = 0; ii < 4; ii++) {
            int row = by * 128 + hi * 64 + ty * 4 + ii;
            #pragma unroll
            for (int hj = 0; hj < 2; hj++) {
                int col = bx * 128 + hj * 64 + tx * 4;
                float4 b4 = *(const float4*)(bias + col);
                float4 o;
                o.x = acc[hi * 4 + ii][hj * 4 + 0] + b4.x;
                o.y = acc[hi * 4 + ii][hj * 4 + 1] + b4.y;
                o.z = acc[hi * 4 + ii][hj * 4 + 2] + b4.z;
                o.w = acc[hi * 4 + ii][hj * 4 + 3] + b4.w;
                *(float4*)(C + (size_t)row * N + col) = o;
            }
        }
    }
}

// ---------------- flash attention: 64x64 tiles, online softmax ----------------
#define APITCH 68
#define ATTN_SMEM (4 * 64 * APITCH * 4)

__global__ __launch_bounds__(256) void attn_kernel(
    const float* __restrict__ Q, const float* __restrict__ Kt,
    const float* __restrict__ V, const float* __restrict__ bias,
    float* __restrict__ O)
{
    extern __shared__ float sm[];
    float* Qs = sm;
    float* Ks = sm + 64 * APITCH;
    float* Vs = sm + 2 * 64 * APITCH;
    float* Ps = sm + 3 * 64 * APITCH;

    const int qt = blockIdx.x;
    const int bh = blockIdx.y;
    const int b = bh >> 4;
    const int h = bh & 15;
    const int qbase = qt * 64;
    const int tid = threadIdx.x;
    const int r = tid >> 2;
    const int c = tid & 3;

    // load Q tile
    const float* Qg = Q + ((size_t)(b * Sz + qbase)) * Hz + h * HDz;
    for (int i = tid; i < 64 * 16; i += 256) {
        int row = i >> 4, c4 = (i & 15) << 2;
        *(float4*)&Qs[row * APITCH + c4] = *(const float4*)&Qg[(size_t)row * Hz + c4];
    }

    float m = -1e30f, l = 0.f;
    float o[16];
    #pragma unroll
    for (int d = 0; d < 16; d++) o[d] = 0.f;

    const float* biasrow = bias + ((size_t)h * BIAS_DIM + (qbase + r)) * BIAS_DIM;
    const float scale = 0.125f;   // 1/sqrt(64)

    for (int t = 0; t < Sz / 64; t++) {
        const int kbase = t * 64;
        __syncthreads();   // protect smem reuse from previous phase C
        const float* Kg = Kt + ((size_t)(b * Sz + kbase)) * Hz + h * HDz;
        const float* Vg = V  + ((size_t)(b * Sz + kbase)) * Hz + h * HDz;
        for (int i = tid; i < 64 * 16; i += 256) {
            int row = i >> 4, c4 = (i & 15) << 2;
            *(float4*)&Ks[row * APITCH + c4] = *(const float4*)&Kg[(size_t)row * Hz + c4];
            *(float4*)&Vs[row * APITCH + c4] = *(const float4*)&Vg[(size_t)row * Hz + c4];
        }
        __syncthreads();

        // phase A: 16 scores per thread
        float s[16];
        float tmax = -1e30f;
        const float* qrow = &Qs[r * APITCH];
        #pragma unroll
        for (int i = 0; i < 16; i++) {
            int kk = (c << 4) + i;
            const float* krow = &Ks[kk * APITCH];
            float acc = 0.f;
            #pragma unroll
            for (int d = 0; d < 64; d += 4) {
                float4 qa = *(const float4*)&qrow[d];
                float4 ka = *(const float4*)&krow[d];
                acc += qa.x * ka.x + qa.y * ka.y + qa.z * ka.z + qa.w * ka.w;
            }
            float sv = acc * scale + __ldg(&biasrow[kbase + kk]);
            s[i] = sv;
            tmax = fmaxf(tmax, sv);
        }

        // phase B: online softmax over 4-lane row groups
        tmax = fmaxf(tmax, __shfl_xor_sync(0xffffffffu, tmax, 1));
        tmax = fmaxf(tmax, __shfl_xor_sync(0xffffffffu, tmax, 2));
        float mnew = fmaxf(m, tmax);
        float corr = __expf(m - mnew);
        float lsum = 0.f;
        #pragma unroll
        for (int i = 0; i < 16; i++) { s[i] = __expf(s[i] - mnew); lsum += s[i]; }
        lsum += __shfl_xor_sync(0xffffffffu, lsum, 1);
        lsum += __shfl_xor_sync(0xffffffffu, lsum, 2);
        l = l * corr + lsum;
        m = mnew;
        #pragma unroll
        for (int d = 0; d < 16; d++) o[d] *= corr;
        #pragma unroll
        for (int i = 0; i < 16; i++) Ps[r * APITCH + (c << 4) + i] = s[i];
        __syncthreads();

        // phase C: O += P @ V (thread owns 16 d-dims)
        const float* prow = &Ps[r * APITCH];
        #pragma unroll 4
        for (int kk = 0; kk < 64; kk++) {
            float pv = prow[kk];
            const float* vrow = &Vs[kk * APITCH + (c << 4)];
            #pragma unroll
            for (int d = 0; d < 16; d += 4) {
                float4 vv = *(const float4*)&vrow[d];
                o[d + 0] += pv * vv.x;
                o[d + 1] += pv * vv.y;
                o[d + 2] += pv * vv.z;
                o[d + 3] += pv * vv.w;
            }
        }
    }

    float inv = 1.f / l;
    float* Og = O + ((size_t)(b * Sz + qbase + r)) * Hz + h * HDz + (c << 4);
    #pragma unroll
    for (int d = 0; d < 16; d += 4) {
        float4 ov;
        ov.x = o[d + 0] * inv;
        ov.y = o[d + 1] * inv;
        ov.z = o[d + 2] * inv;
        ov.w = o[d + 3] * inv;
        *(float4*)&Og[d] = ov;
    }
}

// ---------------- launch ----------------
extern "C" void kernel_launch(void* const* d_in, const int* in_sizes, int n_in,
                              void* d_out, int out_size)
{
    const float* hidden   = (const float*)d_in[0];
    const float* wpb      = (const float*)d_in[1];
    const float* pe_w     = (const float*)d_in[2];
    const float* pe_b     = (const float*)d_in[3];
    const float* pe_g     = (const float*)d_in[4];
    const float* pe_beta  = (const float*)d_in[5];
    const float* norm_g   = (const float*)d_in[6];
    const float* norm_b   = (const float*)d_in[7];
    const float* Wq = (const float*)d_in[8];  const float* bq = (const float*)d_in[9];
    const float* Wk = (const float*)d_in[10]; const float* bk = (const float*)d_in[11];
    const float* Wv = (const float*)d_in[12]; const float* bv = (const float*)d_in[13];
    const float* W1 = (const float*)d_in[14]; const float* b1 = (const float*)d_in[15];
    const float* g1 = (const float*)d_in[16]; const float* be1 = (const float*)d_in[17];
    const float* W2 = (const float*)d_in[18]; const float* b2 = (const float*)d_in[19];
    const float* g2 = (const float*)d_in[20]; const float* be2 = (const float*)d_in[21];
    const float* W3 = (const float*)d_in[22]; const float* b3 = (const float*)d_in[23];
    const float* g3 = (const float*)d_in[24]; const float* be3 = (const float*)d_in[25];
    const float* W4 = (const float*)d_in[26]; const float* b4 = (const float*)d_in[27];
    float* out = (float*)d_out;

    cudaFuncSetAttribute(attn_kernel, cudaFuncAttributeMaxDynamicSharedMemorySize, ATTN_SMEM);

    float* d_pe  = nullptr; cudaGetSymbolAddress((void**)&d_pe,  g_pe);
    float* d_x   = nullptr; cudaGetSymbolAddress((void**)&d_x,   g_x);
    float* d_q   = nullptr; cudaGetSymbolAddress((void**)&d_q,   g_q);
    float* d_k   = nullptr; cudaGetSymbolAddress((void**)&d_k,   g_k);
    float* d_v   = nullptr; cudaGetSymbolAddress((void**)&d_v,   g_v);
    float* d_ctx = nullptr; cudaGetSymbolAddress((void**)&d_ctx, g_ctx);
    float* d_ta  = nullptr; cudaGetSymbolAddress((void**)&d_ta,  g_ta);
    float* d_tb  = nullptr; cudaGetSymbolAddress((void**)&d_tb,  g_tb);

    const int M = Bz * Sz;  // 4096

    pe_kernel<<<Sz, 256>>>(pe_w, pe_b, pe_g, pe_beta, d_pe);
    x_kernel<<<M, 256>>>(hidden, d_pe, norm_g, norm_b, d_x);

    // QKV projections
    sgemm128<<<dim3(Hz / 128, M / 128), 256>>>(d_x, Wq, bq, d_q, M, Hz, Hz);
    sgemm128<<<dim3(Hz / 128, M / 128), 256>>>(d_x, Wk, bk, d_k, M, Hz, Hz);
    sgemm128<<<dim3(Hz / 128, M / 128), 256>>>(d_x, Wv, bv, d_v, M, Hz, Hz);

    // attention
    attn_kernel<<<dim3(Sz / 64, Bz * NHz), 256, ATTN_SMEM>>>(d_q, d_k, d_v, wpb, d_ctx);

    // MLP head
    sgemm128<<<dim3(2 * Hz / 128, M / 128), 256>>>(d_ctx, W1, b1, d_ta, M, 2 * Hz, Hz);
    ln_kernel<<<M, 256>>>(d_ta, d_tb, g1, be1, 2 * Hz, 1);
    sgemm128<<<dim3(2 * Hz / 128, M / 128), 256>>>(d_tb, W2, b2, d_ta, M, 2 * Hz, 2 * Hz);
    ln_kernel<<<M, 256>>>(d_ta, d_tb, g2, be2, 2 * Hz, 1);
    sgemm128<<<dim3(2 * Hz / 128, M / 128), 256>>>(d_tb, W3, b3, d_ta, M, 2 * Hz, 2 * Hz);
    ln_kernel<<<M, 256>>>(d_ta, d_tb, g3, be3, 2 * Hz, 1);
    sgemm128<<<dim3(Hz / 128, M / 128), 256>>>(d_tb, W4, b4, out, M, Hz, 2 * Hz);
}

// round 2
// speedup vs baseline: 2.2173x; 2.2173x over previous
#include <cuda_runtime.h>
#include <cuda_bf16.h>
#include <math.h>

#define Bz 2
#define Sz 2048
#define Hz 1024
#define NHz 16
#define HDz 64
#define BIAS_DIM 2049

// ---------------- scratch (device globals; no allocation) ----------------
__device__ float g_pe[Sz * Hz];
__device__ float g_x[Bz * Sz * Hz];
__device__ float g_q[Bz * Sz * Hz];
__device__ float g_k[Bz * Sz * Hz];
__device__ float g_v[Bz * Sz * Hz];
__device__ float g_ctx[Bz * Sz * Hz];
__device__ float g_ta[Bz * Sz * 2 * Hz];
__device__ float g_tb[Bz * Sz * 2 * Hz];

// ---------------- PE kernel: pe = LN(pos * pe_w + pe_b) ----------------
__global__ __launch_bounds__(256) void pe_kernel(
    const float* __restrict__ pw, const float* __restrict__ pb,
    const float* __restrict__ g, const float* __restrict__ be,
    float* __restrict__ out)
{
    __shared__ float buf[Hz];
    __shared__ float red[8], red2[8];
    __shared__ float s_mean, s_rstd;
    int srow = blockIdx.x;
    int tid = threadIdx.x;
    float pos = ((float)srow - 1024.0f) / (1024.0f + 1e-6f);
    float s = 0.f, ss = 0.f;
    for (int j = tid; j < Hz; j += 256) {
        float v = pos * pw[j] + pb[j];
        buf[j] = v;
        s += v; ss += v * v;
    }
    #pragma unroll
    for (int o = 16; o > 0; o >>= 1) {
        s  += __shfl_down_sync(0xffffffffu, s, o);
        ss += __shfl_down_sync(0xffffffffu, ss, o);
    }
    if ((tid & 31) == 0) { red[tid >> 5] = s; red2[tid >> 5] = ss; }
    __syncthreads();
    if (tid == 0) {
        float S = 0.f, SS = 0.f;
        #pragma unroll
        for (int i = 0; i < 8; i++) { S += red[i]; SS += red2[i]; }
        float mean = S / Hz;
        float var = SS / Hz - mean * mean;
        s_mean = mean;
        s_rstd = rsqrtf(var + 1e-5f);
    }
    __syncthreads();
    float mean = s_mean, rstd = s_rstd;
    float* op = out + (size_t)srow * Hz;
    for (int j = tid; j < Hz; j += 256)
        op[j] = (buf[j] - mean) * rstd * g[j] + be[j];
}

// ---------------- x kernel: x = LN(hidden + pe) ----------------
__global__ __launch_bounds__(256) void x_kernel(
    const float* __restrict__ hidden, const float* __restrict__ pe,
    const float* __restrict__ g, const float* __restrict__ be,
    float* __restrict__ out)
{
    __shared__ float buf[Hz];
    __shared__ float red[8], red2[8];
    __shared__ float s_mean, s_rstd;
    int row = blockIdx.x;
    int srow = row & (Sz - 1);
    int tid = threadIdx.x;
    const float* hp = hidden + (size_t)row * Hz;
    const float* pp = pe + (size_t)srow * Hz;
    float s = 0.f, ss = 0.f;
    for (int j = tid; j < Hz; j += 256) {
        float v = hp[j] + pp[j];
        buf[j] = v;
        s += v; ss += v * v;
    }
    #pragma unroll
    for (int o = 16; o > 0; o >>= 1) {
        s  += __shfl_down_sync(0xffffffffu, s, o);
        ss += __shfl_down_sync(0xffffffffu, ss, o);
    }
    if ((tid & 31) == 0) { red[tid >> 5] = s; red2[tid >> 5] = ss; }
    __syncthreads();
    if (tid == 0) {
        float S = 0.f, SS = 0.f;
        #pragma unroll
        for (int i = 0; i < 8; i++) { S += red[i]; SS += red2[i]; }
        float mean = S / Hz;
        float var = SS / Hz - mean * mean;
        s_mean = mean;
        s_rstd = rsqrtf(var + 1e-5f);
    }
    __syncthreads();
    float mean = s_mean, rstd = s_rstd;
    float* op = out + (size_t)row * Hz;
    for (int j = tid; j < Hz; j += 256)
        op[j] = (buf[j] - mean) * rstd * g[j] + be[j];
}

// ---------------- LN (+optional ReLU) over rows of length N ----------------
__global__ __launch_bounds__(256) void ln_kernel(
    const float* __restrict__ in, float* __restrict__ out,
    const float* __restrict__ g, const float* __restrict__ be,
    int N, int relu)
{
    __shared__ float buf[2 * Hz];
    __shared__ float red[8], red2[8];
    __shared__ float s_mean, s_rstd;
    int row = blockIdx.x;
    int tid = threadIdx.x;
    const float* ip = in + (size_t)row * N;
    float s = 0.f, ss = 0.f;
    for (int j = tid; j < N; j += 256) {
        float v = ip[j];
        buf[j] = v;
        s += v; ss += v * v;
    }
    #pragma unroll
    for (int o = 16; o > 0; o >>= 1) {
        s  += __shfl_down_sync(0xffffffffu, s, o);
        ss += __shfl_down_sync(0xffffffffu, ss, o);
    }
    if ((tid & 31) == 0) { red[tid >> 5] = s; red2[tid >> 5] = ss; }
    __syncthreads();
    if (tid == 0) {
        float S = 0.f, SS = 0.f;
        #pragma unroll
        for (int i = 0; i < 8; i++) { S += red[i]; SS += red2[i]; }
        float mean = S / N;
        float var = SS / N - mean * mean;
        s_mean = mean;
        s_rstd = rsqrtf(var + 1e-5f);
    }
    __syncthreads();
    float mean = s_mean, rstd = s_rstd;
    float* op = out + (size_t)row * N;
    for (int j = tid; j < N; j += 256) {
        float v = (buf[j] - mean) * rstd * g[j] + be[j];
        if (relu) v = fmaxf(v, 0.f);
        op[j] = v;
    }
}

// ---------------- SGEMM (double-buffered): C = A @ B + bias ----------------
__global__ __launch_bounds__(256) void sgemm128(
    const float* __restrict__ A, const float* __restrict__ Bm,
    const float* __restrict__ bias, float* __restrict__ C,
    int M, int N, int K)
{
    __shared__ float As[2][8][128];
    __shared__ float Bs[2][8][128];
    const int bx = blockIdx.x;
    const int by = blockIdx.y;
    const int tid = threadIdx.x;
    const int tx = tid & 15;
    const int ty = tid >> 4;

    float acc[8][8];
    #pragma unroll
    for (int i = 0; i < 8; i++)
        #pragma unroll
        for (int j = 0; j < 8; j++) acc[i][j] = 0.f;

    const float* Ab = A + (size_t)by * 128 * K;
    const float* Bb = Bm + (size_t)bx * 128;

    const int arow = tid >> 1;
    const int acol = (tid & 1) << 2;
    const int brow = tid >> 5;
    const int bcol = (tid & 31) << 2;

    // preload k-tile 0
    {
        float4 a4 = *(const float4*)(Ab + (size_t)arow * K + acol);
        As[0][acol + 0][arow] = a4.x;
        As[0][acol + 1][arow] = a4.y;
        As[0][acol + 2][arow] = a4.z;
        As[0][acol + 3][arow] = a4.w;
        *(float4*)(&Bs[0][brow][bcol]) = *(const float4*)(Bb + (size_t)brow * N + bcol);
    }
    __syncthreads();

    int buf = 0;
    for (int kt = 0; kt < K; kt += 8) {
        const bool more = (kt + 8) < K;
        float4 a4n, b4n;
        if (more) {
            a4n = *(const float4*)(Ab + (size_t)arow * K + kt + 8 + acol);
            b4n = *(const float4*)(Bb + (size_t)(kt + 8 + brow) * N + bcol);
        }
        #pragma unroll
        for (int k = 0; k < 8; k++) {
            float ar[8], br[8];
            *(float4*)(ar)     = *(const float4*)(&As[buf][k][ty * 4]);
            *(float4*)(ar + 4) = *(const float4*)(&As[buf][k][64 + ty * 4]);
            *(float4*)(br)     = *(const float4*)(&Bs[buf][k][tx * 4]);
            *(float4*)(br + 4) = *(const float4*)(&Bs[buf][k][64 + tx * 4]);
            #pragma unroll
            for (int i = 0; i < 8; i++)
                #pragma unroll
                for (int j = 0; j < 8; j++)
                    acc[i][j] += ar[i] * br[j];
        }
        if (more) {
            As[buf ^ 1][acol + 0][arow] = a4n.x;
            As[buf ^ 1][acol + 1][arow] = a4n.y;
            As[buf ^ 1][acol + 2][arow] = a4n.z;
            As[buf ^ 1][acol + 3][arow] = a4n.w;
            *(float4*)(&Bs[buf ^ 1][brow][bcol]) = b4n;
        }
        __syncthreads();
        buf ^= 1;
    }

    #pragma unroll
    for (int hi = 0; hi < 2; hi++) {
        #pragma unroll
        for (int ii = 0; ii < 4; ii++) {
            int row = by * 128 + hi * 64 + ty * 4 + ii;
            #pragma unroll
            for (int hj = 0; hj < 2; hj++) {
                int col = bx * 128 + hj * 64 + tx * 4;
                float4 b4 = *(const float4*)(bias + col);
                float4 o;
                o.x = acc[hi * 4 + ii][hj * 4 + 0] + b4.x;
                o.y = acc[hi * 4 + ii][hj * 4 + 1] + b4.y;
                o.z = acc[hi * 4 + ii][hj * 4 + 2] + b4.z;
                o.w = acc[hi * 4 + ii][hj * 4 + 3] + b4.w;
                *(float4*)(C + (size_t)row * N + col) = o;
            }
        }
    }
}

// ---------------- flash attention v2: Br=128, Bc=64, 8x4 micro-tile ----------------
#define AP 68
#define ATTN2_SMEM ((128 + 64 + 64 + 128) * AP * 4)

__global__ __launch_bounds__(256) void attn2_kernel(
    const float* __restrict__ Q, const float* __restrict__ Kt,
    const float* __restrict__ V, const float* __restrict__ bias,
    float* __restrict__ O)
{
    extern __shared__ float sm[];
    float* Qs = sm;                    // [128][AP]  natural (row, d)
    float* Ks = sm + 128 * AP;         // [64][AP]   transposed (d, token)
    float* Vs = Ks + 64 * AP;          // [64][AP]   natural (token, d)
    float* Ps = Vs + 64 * AP;          // [128][AP]  natural (row, token)

    const int qt = blockIdx.x;
    const int bh = blockIdx.y;
    const int b = bh >> 4;
    const int h = bh & 15;
    const int qbase = qt * 128;
    const int tid = threadIdx.x;
    const int tx = tid & 15;            // N-direction (cols, x4)
    const int ty = tid >> 4;            // M-direction (rows, x8)

    // load Q tile [128][64], natural layout
    const float* Qg = Q + ((size_t)(b * Sz + qbase)) * Hz + h * HDz;
    #pragma unroll
    for (int s = 0; s < 8; s++) {
        int f = s * 256 + tid;
        int row = f >> 4, c4 = (f & 15) << 2;
        *(float4*)&Qs[row * AP + c4] = *(const float4*)&Qg[(size_t)row * Hz + c4];
    }

    float m[8], l[8], o[8][4];
    #pragma unroll
    for (int i = 0; i < 8; i++) {
        m[i] = -1e30f; l[i] = 0.f;
        #pragma unroll
        for (int j = 0; j < 4; j++) o[i][j] = 0.f;
    }

    const float* biasrow = bias + ((size_t)h * BIAS_DIM + qbase) * BIAS_DIM;
    const float scale = 0.125f;   // 1/sqrt(64)

    for (int t = 0; t < Sz / 64; t++) {
        const int kbase = t * 64;
        __syncthreads();   // protect smem reuse
        const float* Kg = Kt + ((size_t)(b * Sz + kbase)) * Hz + h * HDz;
        const float* Vg = V  + ((size_t)(b * Sz + kbase)) * Hz + h * HDz;
        #pragma unroll
        for (int s = 0; s < 4; s++) {
            int f = s * 256 + tid;
            // K: read float4 along d, store transposed (2-way STS conflicts only)
            int token = (f >> 2) & 63;
            int d = ((f & 3) | ((f >> 8) << 2)) << 2;
            float4 kv = *(const float4*)&Kg[(size_t)token * Hz + d];
            Ks[(d + 0) * AP + token] = kv.x;
            Ks[(d + 1) * AP + token] = kv.y;
            Ks[(d + 2) * AP + token] = kv.z;
            Ks[(d + 3) * AP + token] = kv.w;
            // V: natural copy
            int row = f >> 4, c4 = (f & 15) << 2;
            *(float4*)&Vs[row * AP + c4] = *(const float4*)&Vg[(size_t)row * Hz + c4];
        }
        __syncthreads();

        // ---- phase A: S = Q @ K^T (8x4 per thread) ----
        float s_[8][4];
        #pragma unroll
        for (int i = 0; i < 8; i++)
            #pragma unroll
            for (int j = 0; j < 4; j++) s_[i][j] = 0.f;

        #pragma unroll 4
        for (int d = 0; d < 64; d++) {
            float bf[4];
            *(float4*)bf = *(const float4*)&Ks[d * AP + (tx << 2)];
            float af[8];
            #pragma unroll
            for (int i = 0; i < 8; i++) af[i] = Qs[(ty * 8 + i) * AP + d];
            #pragma unroll
            for (int i = 0; i < 8; i++) {
                s_[i][0] += af[i] * bf[0];
                s_[i][1] += af[i] * bf[1];
                s_[i][2] += af[i] * bf[2];
                s_[i][3] += af[i] * bf[3];
            }
        }

        // ---- phase B: bias + online softmax ----
        #pragma unroll
        for (int i = 0; i < 8; i++) {
            const float* bp = biasrow + (size_t)(ty * 8 + i) * BIAS_DIM + kbase + (tx << 2);
            float sv0 = s_[i][0] * scale + __ldg(bp + 0);
            float sv1 = s_[i][1] * scale + __ldg(bp + 1);
            float sv2 = s_[i][2] * scale + __ldg(bp + 2);
            float sv3 = s_[i][3] * scale + __ldg(bp + 3);
            float rowm = fmaxf(fmaxf(sv0, sv1), fmaxf(sv2, sv3));
            rowm = fmaxf(rowm, __shfl_xor_sync(0xffffffffu, rowm, 1));
            rowm = fmaxf(rowm, __shfl_xor_sync(0xffffffffu, rowm, 2));
            rowm = fmaxf(rowm, __shfl_xor_sync(0xffffffffu, rowm, 4));
            rowm = fmaxf(rowm, __shfl_xor_sync(0xffffffffu, rowm, 8));
            float mnew = fmaxf(m[i], rowm);
            float corr = __expf(m[i] - mnew);
            m[i] = mnew;
            float p0 = __expf(sv0 - mnew);
            float p1 = __expf(sv1 - mnew);
            float p2 = __expf(sv2 - mnew);
            float p3 = __expf(sv3 - mnew);
            float rs = p0 + p1 + p2 + p3;
            rs += __shfl_xor_sync(0xffffffffu, rs, 1);
            rs += __shfl_xor_sync(0xffffffffu, rs, 2);
            rs += __shfl_xor_sync(0xffffffffu, rs, 4);
            rs += __shfl_xor_sync(0xffffffffu, rs, 8);
            l[i] = l[i] * corr + rs;
            o[i][0] *= corr; o[i][1] *= corr; o[i][2] *= corr; o[i][3] *= corr;
            float4 pv = make_float4(p0, p1, p2, p3);
            *(float4*)&Ps[(ty * 8 + i) * AP + (tx << 2)] = pv;
        }
        __syncthreads();

        // ---- phase C: O += P @ V ----
        #pragma unroll 4
        for (int kk = 0; kk < 64; kk++) {
            float bf[4];
            *(float4*)bf = *(const float4*)&Vs[kk * AP + (tx << 2)];
            float af[8];
            #pragma unroll
            for (int i = 0; i < 8; i++) af[i] = Ps[(ty * 8 + i) * AP + kk];
            #pragma unroll
            for (int i = 0; i < 8; i++) {
                o[i][0] += af[i] * bf[0];
                o[i][1] += af[i] * bf[1];
                o[i][2] += af[i] * bf[2];
                o[i][3] += af[i] * bf[3];
            }
        }
    }

    // epilogue
    #pragma unroll
    for (int i = 0; i < 8; i++) {
        float inv = 1.f / l[i];
        float4 ov;
        ov.x = o[i][0] * inv;
        ov.y = o[i][1] * inv;
        ov.z = o[i][2] * inv;
        ov.w = o[i][3] * inv;
        float* Og = O + ((size_t)(b * Sz + qbase + ty * 8 + i)) * Hz + h * HDz + (tx << 2);
        *(float4*)Og = ov;
    }
}

// ---------------- launch ----------------
extern "C" void kernel_launch(void* const* d_in, const int* in_sizes, int n_in,
                              void* d_out, int out_size)
{
    const float* hidden   = (const float*)d_in[0];
    const float* wpb      = (const float*)d_in[1];
    const float* pe_w     = (const float*)d_in[2];
    const float* pe_b     = (const float*)d_in[3];
    const float* pe_g     = (const float*)d_in[4];
    const float* pe_beta  = (const float*)d_in[5];
    const float* norm_g   = (const float*)d_in[6];
    const float* norm_b   = (const float*)d_in[7];
    const float* Wq = (const float*)d_in[8];  const float* bq = (const float*)d_in[9];
    const float* Wk = (const float*)d_in[10]; const float* bk = (const float*)d_in[11];
    const float* Wv = (const float*)d_in[12]; const float* bv = (const float*)d_in[13];
    const float* W1 = (const float*)d_in[14]; const float* b1 = (const float*)d_in[15];
    const float* g1 = (const float*)d_in[16]; const float* be1 = (const float*)d_in[17];
    const float* W2 = (const float*)d_in[18]; const float* b2 = (const float*)d_in[19];
    const float* g2 = (const float*)d_in[20]; const float* be2 = (const float*)d_in[21];
    const float* W3 = (const float*)d_in[22]; const float* b3 = (const float*)d_in[23];
    const float* g3 = (const float*)d_in[24]; const float* be3 = (const float*)d_in[25];
    const float* W4 = (const float*)d_in[26]; const float* b4 = (const float*)d_in[27];
    float* out = (float*)d_out;

    cudaFuncSetAttribute(attn2_kernel, cudaFuncAttributeMaxDynamicSharedMemorySize, ATTN2_SMEM);

    float* d_pe  = nullptr; cudaGetSymbolAddress((void**)&d_pe,  g_pe);
    float* d_x   = nullptr; cudaGetSymbolAddress((void**)&d_x,   g_x);
    float* d_q   = nullptr; cudaGetSymbolAddress((void**)&d_q,   g_q);
    float* d_k   = nullptr; cudaGetSymbolAddress((void**)&d_k,   g_k);
    float* d_v   = nullptr; cudaGetSymbolAddress((void**)&d_v,   g_v);
    float* d_ctx = nullptr; cudaGetSymbolAddress((void**)&d_ctx, g_ctx);
    float* d_ta  = nullptr; cudaGetSymbolAddress((void**)&d_ta,  g_ta);
    float* d_tb  = nullptr; cudaGetSymbolAddress((void**)&d_tb,  g_tb);

    const int M = Bz * Sz;  // 4096

    pe_kernel<<<Sz, 256>>>(pe_w, pe_b, pe_g, pe_beta, d_pe);
    x_kernel<<<M, 256>>>(hidden, d_pe, norm_g, norm_b, d_x);

    // QKV projections
    sgemm128<<<dim3(Hz / 128, M / 128), 256>>>(d_x, Wq, bq, d_q, M, Hz, Hz);
    sgemm128<<<dim3(Hz / 128, M / 128), 256>>>(d_x, Wk, bk, d_k, M, Hz, Hz);
    sgemm128<<<dim3(Hz / 128, M / 128), 256>>>(d_x, Wv, bv, d_v, M, Hz, Hz);

    // attention
    attn2_kernel<<<dim3(Sz / 128, Bz * NHz), 256, ATTN2_SMEM>>>(d_q, d_k, d_v, wpb, d_ctx);

    // MLP head
    sgemm128<<<dim3(2 * Hz / 128, M / 128), 256>>>(d_ctx, W1, b1, d_ta, M, 2 * Hz, Hz);
    ln_kernel<<<M, 256>>>(d_ta, d_tb, g1, be1, 2 * Hz, 1);
    sgemm128<<<dim3(2 * Hz / 128, M / 128), 256>>>(d_tb, W2, b2, d_ta, M, 2 * Hz, 2 * Hz);
    ln_kernel<<<M, 256>>>(d_ta, d_tb, g2, be2, 2 * Hz, 1);
    sgemm128<<<dim3(2 * Hz / 128, M / 128), 256>>>(d_tb, W3, b3, d_ta, M, 2 * Hz, 2 * Hz);
    ln_kernel<<<M, 256>>>(d_ta, d_tb, g3, be3, 2 * Hz, 1);
    sgemm128<<<dim3(Hz / 128, M / 128), 256>>>(d_tb, W4, b4, out, M, Hz, 2 * Hz);
}

// round 5
// speedup vs baseline: 4.9378x; 2.2270x over previous
#include <cuda_runtime.h>
#include <cuda_bf16.h>
#include <math.h>
#include <stdint.h>

#define Bz 2
#define Sz 2048
#define Hz 1024
#define NHz 16
#define HDz 64
#define BIAS_DIM 2049

typedef __nv_bfloat16 bf16;

// Does this device-compilation pass have the arch-specific (tcgen05) feature set?
#if defined(__CUDA_ARCH_FEAT_SM103_ALL) || defined(__CUDA_ARCH_FEAT_SM100_ALL)
#define USE_TCGEN05 1
#else
#define USE_TCGEN05 0
#endif

// ---------------- scratch (device globals; no allocation) ----------------
__device__ float g_pe[Sz * Hz];
__device__ float g_q[Bz * Sz * Hz];
__device__ float g_k[Bz * Sz * Hz];
__device__ float g_v[Bz * Sz * Hz];
__device__ float g_ta[Bz * Sz * 2 * Hz];

__device__ bf16 g_xh[Bz * Sz * Hz];
__device__ bf16 g_xl[Bz * Sz * Hz];
__device__ bf16 g_cth[Bz * Sz * Hz];
__device__ bf16 g_ctl[Bz * Sz * Hz];
__device__ bf16 g_tah[Bz * Sz * 2 * Hz];
__device__ bf16 g_tal[Bz * Sz * 2 * Hz];

// transposed split weights: [N][K]
__device__ bf16 g_wqh[Hz * Hz],      g_wql[Hz * Hz];
__device__ bf16 g_wkh[Hz * Hz],      g_wkl[Hz * Hz];
__device__ bf16 g_wvh[Hz * Hz],      g_wvl[Hz * Hz];
__device__ bf16 g_w1h[2 * Hz * Hz],  g_w1l[2 * Hz * Hz];
__device__ bf16 g_w2h[4 * Hz * Hz],  g_w2l[4 * Hz * Hz];
__device__ bf16 g_w3h[4 * Hz * Hz],  g_w3l[4 * Hz * Hz];
__device__ bf16 g_w4h[2 * Hz * Hz],  g_w4l[2 * Hz * Hz];

// ---------------- common helpers ----------------
__device__ __forceinline__ uint32_t smem_u32(const void* p) {
    uint32_t a;
    asm("{ .reg .u64 t; cvta.to.shared.u64 t, %1; cvt.u32.u64 %0, t; }" : "=r"(a) : "l"(p));
    return a;
}
__device__ __forceinline__ void bsplit(float v, bf16& h, bf16& l) {
    h = __float2bfloat16(v);
    l = __float2bfloat16(v - __bfloat162float(h));
}

#if USE_TCGEN05
// ---------------- tcgen05 helpers (only in 'a'-feature passes) ----------------
__device__ __forceinline__ uint32_t elect_one_pred() {
    uint32_t pred;
    asm volatile("{\n\t.reg .pred p;\n\telect.sync _|p, 0xFFFFFFFF;\n\tselp.b32 %0, 1, 0, p;\n\t}" : "=r"(pred));
    return pred;
}
#define MBARRIER_INIT(a, n) \
    asm volatile("mbarrier.init.shared.b64 [%0], %1;" :: "r"((uint32_t)(a)), "r"((uint32_t)(n)) : "memory")
#define MBARRIER_WAIT_PARITY(a, ph) do { \
    uint32_t _m = (uint32_t)(a); uint32_t _p = (uint32_t)(ph); uint32_t _d; \
    asm volatile("{\n\t.reg .pred p;\n\tmbarrier.try_wait.parity.acquire.cta.shared::cta.b64 p, [%1], %2;\n\tselp.b32 %0, 1, 0, p;\n\t}" \
        : "=r"(_d) : "r"(_m), "r"(_p) : "memory"); \
    if (!_d) { \
        asm volatile("{\n\t.reg .pred P1;\n\tWL_%=:\n\tmbarrier.try_wait.parity.acquire.cta.shared::cta.b64 P1, [%0], %1, 0x989680;\n\t@P1 bra.uni WD_%=;\n\tbra.uni WL_%=;\n\tWD_%=:\n\t}" \
            :: "r"(_m), "r"(_p) : "memory"); \
    } } while (0)
#define TCGEN05_ALLOC(sa, n) \
    asm volatile("tcgen05.alloc.cta_group::1.sync.aligned.shared::cta.b32 [%0], %1;" :: "r"((uint32_t)(sa)), "r"((uint32_t)(n)) : "memory")
#define TCGEN05_DEALLOC(t, n) \
    asm volatile("tcgen05.dealloc.cta_group::1.sync.aligned.b32 %0, %1;" :: "r"(t), "r"((uint32_t)(n)))
#define TCGEN05_COMMIT(a) \
    asm volatile("tcgen05.commit.cta_group::1.mbarrier::arrive::one.shared::cluster.b64 [%0];" :: "r"((uint32_t)(a)) : "memory")
#define TCGEN05_FENCE_AFTER() asm volatile("tcgen05.fence::after_thread_sync;" ::: "memory")
#define TCGEN05_WAIT_LD() asm volatile("tcgen05.wait::ld.sync.aligned;" ::: "memory")
#define FENCE_PROXY_ASYNC() asm volatile("fence.proxy.async.shared::cta;" ::: "memory")

#define TCGEN05_LD_32X32B_X32(r, ta) \
    asm volatile( \
        "tcgen05.ld.sync.aligned.32x32b.x32.b32 " \
        "{%0, %1, %2, %3, %4, %5, %6, %7, " \
        " %8, %9, %10, %11, %12, %13, %14, %15, " \
        " %16, %17, %18, %19, %20, %21, %22, %23, " \
        " %24, %25, %26, %27, %28, %29, %30, %31}, [%32];" \
        : "=r"((r)[0]),  "=r"((r)[1]),  "=r"((r)[2]),  "=r"((r)[3]), \
          "=r"((r)[4]),  "=r"((r)[5]),  "=r"((r)[6]),  "=r"((r)[7]), \
          "=r"((r)[8]),  "=r"((r)[9]),  "=r"((r)[10]), "=r"((r)[11]), \
          "=r"((r)[12]), "=r"((r)[13]), "=r"((r)[14]), "=r"((r)[15]), \
          "=r"((r)[16]), "=r"((r)[17]), "=r"((r)[18]), "=r"((r)[19]), \
          "=r"((r)[20]), "=r"((r)[21]), "=r"((r)[22]), "=r"((r)[23]), \
          "=r"((r)[24]), "=r"((r)[25]), "=r"((r)[26]), "=r"((r)[27]), \
          "=r"((r)[28]), "=r"((r)[29]), "=r"((r)[30]), "=r"((r)[31]) \
        : "r"(ta))

__device__ __forceinline__ void mma_f16_ss(uint32_t d, uint64_t ad, uint64_t bd,
                                           uint32_t idesc, uint32_t en) {
    asm volatile(
        "{\n\t.reg .pred p;\n\tsetp.ne.u32 p, %5, 0;\n\t"
        "tcgen05.mma.cta_group::1.kind::f16 [%0], %1, %2, %3, {%4, %4, %4, %4}, p;\n\t}"
        :: "r"(d), "l"(ad), "l"(bd), "r"(idesc), "r"(0u), "r"(en) : "memory");
}
__device__ __forceinline__ uint64_t mkdesc(uint32_t addr) {
    const uint64_t base = (2ull << 61) | (1ull << 46) | (64ull << 32) | (1ull << 16);
    return base | ((uint64_t)(addr >> 4) & 0x3FFF);
}
#endif  // USE_TCGEN05

// ---------------- mma.sync fallback helpers (legal from compute_80) ----------------
__device__ __forceinline__ void cpa16(uint32_t d, const void* g) {
    asm volatile("cp.async.cg.shared.global [%0], [%1], 16;" :: "r"(d), "l"(g));
}
#define CP_COMMIT() asm volatile("cp.async.commit_group;" ::: "memory")
#define CP_WAIT0()  asm volatile("cp.async.wait_group 0;" ::: "memory")

__device__ __forceinline__ void ldsm4(uint32_t& a0, uint32_t& a1, uint32_t& a2, uint32_t& a3, uint32_t addr) {
    asm volatile("ldmatrix.sync.aligned.m8n8.x4.shared.b16 {%0,%1,%2,%3}, [%4];"
        : "=r"(a0), "=r"(a1), "=r"(a2), "=r"(a3) : "r"(addr));
}
__device__ __forceinline__ void ldsm2(uint32_t& a0, uint32_t& a1, uint32_t addr) {
    asm volatile("ldmatrix.sync.aligned.m8n8.x2.shared.b16 {%0,%1}, [%2];"
        : "=r"(a0), "=r"(a1) : "r"(addr));
}
__device__ __forceinline__ void mma16816(float* c, uint32_t a0, uint32_t a1, uint32_t a2, uint32_t a3,
                                         uint32_t b0, uint32_t b1) {
    asm volatile("mma.sync.aligned.m16n8k16.row.col.f32.bf16.bf16.f32 "
        "{%0,%1,%2,%3}, {%4,%5,%6,%7}, {%8,%9}, {%0,%1,%2,%3};"
        : "+f"(c[0]), "+f"(c[1]), "+f"(c[2]), "+f"(c[3])
        : "r"(a0), "r"(a1), "r"(a2), "r"(a3), "r"(b0), "r"(b1));
}

// ---------------- PE kernel ----------------
__global__ __launch_bounds__(256) void pe_kernel(
    const float* __restrict__ pw, const float* __restrict__ pb,
    const float* __restrict__ g, const float* __restrict__ be,
    float* __restrict__ out)
{
    __shared__ float buf[Hz];
    __shared__ float red[8], red2[8];
    __shared__ float s_mean, s_rstd;
    int srow = blockIdx.x;
    int tid = threadIdx.x;
    float pos = ((float)srow - 1024.0f) / (1024.0f + 1e-6f);
    float s = 0.f, ss = 0.f;
    for (int j = tid; j < Hz; j += 256) {
        float v = pos * pw[j] + pb[j];
        buf[j] = v;
        s += v; ss += v * v;
    }
    #pragma unroll
    for (int o = 16; o > 0; o >>= 1) {
        s  += __shfl_down_sync(0xffffffffu, s, o);
        ss += __shfl_down_sync(0xffffffffu, ss, o);
    }
    if ((tid & 31) == 0) { red[tid >> 5] = s; red2[tid >> 5] = ss; }
    __syncthreads();
    if (tid == 0) {
        float S = 0.f, SS = 0.f;
        #pragma unroll
        for (int i = 0; i < 8; i++) { S += red[i]; SS += red2[i]; }
        float mean = S / Hz;
        float var = SS / Hz - mean * mean;
        s_mean = mean;
        s_rstd = rsqrtf(var + 1e-5f);
    }
    __syncthreads();
    float mean = s_mean, rstd = s_rstd;
    float* op = out + (size_t)srow * Hz;
    for (int j = tid; j < Hz; j += 256)
        op[j] = (buf[j] - mean) * rstd * g[j] + be[j];
}

// ---------------- x kernel: split(LN(hidden + pe)) ----------------
__global__ __launch_bounds__(256) void x_kernel(
    const float* __restrict__ hidden, const float* __restrict__ pe,
    const float* __restrict__ g, const float* __restrict__ be,
    bf16* __restrict__ oh, bf16* __restrict__ ol)
{
    __shared__ float buf[Hz];
    __shared__ float red[8], red2[8];
    __shared__ float s_mean, s_rstd;
    int row = blockIdx.x;
    int srow = row & (Sz - 1);
    int tid = threadIdx.x;
    const float* hp = hidden + (size_t)row * Hz;
    const float* pp = pe + (size_t)srow * Hz;
    float s = 0.f, ss = 0.f;
    for (int j = tid; j < Hz; j += 256) {
        float v = hp[j] + pp[j];
        buf[j] = v;
        s += v; ss += v * v;
    }
    #pragma unroll
    for (int o = 16; o > 0; o >>= 1) {
        s  += __shfl_down_sync(0xffffffffu, s, o);
        ss += __shfl_down_sync(0xffffffffu, ss, o);
    }
    if ((tid & 31) == 0) { red[tid >> 5] = s; red2[tid >> 5] = ss; }
    __syncthreads();
    if (tid == 0) {
        float S = 0.f, SS = 0.f;
        #pragma unroll
        for (int i = 0; i < 8; i++) { S += red[i]; SS += red2[i]; }
        float mean = S / Hz;
        float var = SS / Hz - mean * mean;
        s_mean = mean;
        s_rstd = rsqrtf(var + 1e-5f);
    }
    __syncthreads();
    float mean = s_mean, rstd = s_rstd;
    bf16* ohp = oh + (size_t)row * Hz;
    bf16* olp = ol + (size_t)row * Hz;
    for (int j = tid; j < Hz; j += 256) {
        float v = (buf[j] - mean) * rstd * g[j] + be[j];
        bf16 h, l;
        bsplit(v, h, l);
        ohp[j] = h; olp[j] = l;
    }
}

// ---------------- LN + ReLU + split ----------------
__global__ __launch_bounds__(256) void ln_split_kernel(
    const float* __restrict__ in,
    bf16* __restrict__ oh, bf16* __restrict__ ol,
    const float* __restrict__ g, const float* __restrict__ be, int N)
{
    __shared__ float buf[2 * Hz];
    __shared__ float red[8], red2[8];
    __shared__ float s_mean, s_rstd;
    int row = blockIdx.x;
    int tid = threadIdx.x;
    const float* ip = in + (size_t)row * N;
    float s = 0.f, ss = 0.f;
    for (int j = tid; j < N; j += 256) {
        float v = ip[j];
        buf[j] = v;
        s += v; ss += v * v;
    }
    #pragma unroll
    for (int o = 16; o > 0; o >>= 1) {
        s  += __shfl_down_sync(0xffffffffu, s, o);
        ss += __shfl_down_sync(0xffffffffu, ss, o);
    }
    if ((tid & 31) == 0) { red[tid >> 5] = s; red2[tid >> 5] = ss; }
    __syncthreads();
    if (tid == 0) {
        float S = 0.f, SS = 0.f;
        #pragma unroll
        for (int i = 0; i < 8; i++) { S += red[i]; SS += red2[i]; }
        float mean = S / N;
        float var = SS / N - mean * mean;
        s_mean = mean;
        s_rstd = rsqrtf(var + 1e-5f);
    }
    __syncthreads();
    float mean = s_mean, rstd = s_rstd;
    bf16* ohp = oh + (size_t)row * N;
    bf16* olp = ol + (size_t)row * N;
    for (int j = tid; j < N; j += 256) {
        float v = (buf[j] - mean) * rstd * g[j] + be[j];
        v = fmaxf(v, 0.f);
        bf16 h, l;
        bsplit(v, h, l);
        ohp[j] = h; olp[j] = l;
    }
}

// ---------------- weight transpose + split: W[K][N] -> T[N][K] hi/lo ----------------
__global__ __launch_bounds__(256) void wsplit_kernel(
    const float* __restrict__ W, bf16* __restrict__ Th, bf16* __restrict__ Tl,
    int K, int N)
{
    __shared__ float t[32][33];
    int bx = blockIdx.x;
    int by = blockIdx.y;
    int tx = threadIdx.x & 31, ty = threadIdx.x >> 5;
    #pragma unroll
    for (int i = 0; i < 32; i += 8)
        t[ty + i][tx] = W[(size_t)(by * 32 + ty + i) * N + bx * 32 + tx];
    __syncthreads();
    #pragma unroll
    for (int i = 0; i < 32; i += 8) {
        float v = t[tx][ty + i];
        size_t o = (size_t)(bx * 32 + ty + i) * K + by * 32 + tx;
        bf16 h, l;
        bsplit(v, h, l);
        Th[o] = h; Tl[o] = l;
    }
}

// ---------------- GEMM: C[M,N] = A @ B^T + bias (dual path) ----------------
// A (hi/lo): [M][K] bf16; Bt (hi/lo): [N][K] bf16; C fp32. Tile 128x128.
#define GTM 128
#define GTN 128
#define G_TILE_B 16384
#define G_STAGE_B (4 * G_TILE_B)
#define GEMM_SMEM (1024 + 2 * G_STAGE_B)
#define G_IDESC ((1u << 4) | (1u << 7) | (1u << 10) | ((GTN / 8) << 17) | ((GTM / 16) << 24))

__global__ __launch_bounds__(256, 1) void gemm_tc(
    const bf16* __restrict__ Ah, const bf16* __restrict__ Al,
    const bf16* __restrict__ Bh, const bf16* __restrict__ Bl,
    const float* __restrict__ bias, float* __restrict__ C,
    int M, int N, int K)
{
#if USE_TCGEN05
    // ======== tcgen05 path (128x128 tile, TK=64, double-buffered) ========
    extern __shared__ char smem[];
    const uint32_t sb = smem_u32(smem);
    const int tid = threadIdx.x;
    const int wid = tid >> 5;
    const int lid = tid & 31;
    const int bx = blockIdx.x, by = blockIdx.y;

    if (wid == 0) TCGEN05_ALLOC(sb, 128);
    if (tid == 0) {
        MBARRIER_INIT(sb + 8, 1);
        MBARRIER_INIT(sb + 16, 1);
    }
    __syncthreads();
    uint32_t tmem;
    asm volatile("ld.shared.b32 %0, [%1];" : "=r"(tmem) : "r"(sb));

    const bf16* Agh = Ah + (size_t)(by * GTM) * K;
    const bf16* Agl = Al + (size_t)(by * GTM) * K;
    const bf16* Bgh = Bh + (size_t)(bx * GTN) * K;
    const bf16* Bgl = Bl + (size_t)(bx * GTN) * K;

    const int nc = K / 64;
    int pw0 = 0, pw1 = 0;

    for (int c = 0; c < nc; c++) {
        const int b = c & 1;
        if (c >= 2) {
            if (b == 0) { MBARRIER_WAIT_PARITY(sb + 8, pw0);  pw0 ^= 1; }
            else        { MBARRIER_WAIT_PARITY(sb + 16, pw1); pw1 ^= 1; }
        }
        char* st = smem + 1024 + b * G_STAGE_B;
        const int kt = c * 64;
        #pragma unroll
        for (int i = 0; i < 4; i++) {
            int f = i * 256 + tid;
            int row = f >> 3, q = f & 7;
            uint32_t off = (row << 7) + (q << 4);
            uint32_t sw = off ^ ((off >> 3) & 0x70);
            uint4 va = ((const uint4*)(Agh + (size_t)row * K + kt))[q];
            *(uint4*)(st + sw) = va;
            uint4 vb = ((const uint4*)(Agl + (size_t)row * K + kt))[q];
            *(uint4*)(st + G_TILE_B + sw) = vb;
            uint4 vc = ((const uint4*)(Bgh + (size_t)row * K + kt))[q];
            *(uint4*)(st + 2 * G_TILE_B + sw) = vc;
            uint4 vd = ((const uint4*)(Bgl + (size_t)row * K + kt))[q];
            *(uint4*)(st + 3 * G_TILE_B + sw) = vd;
        }
        __syncthreads();
        if (wid == 0 && elect_one_pred()) {
            FENCE_PROXY_ASYNC();
            uint32_t s0 = sb + 1024 + b * G_STAGE_B;
            uint64_t dAh = mkdesc(s0);
            uint64_t dAl = mkdesc(s0 + G_TILE_B);
            uint64_t dBh = mkdesc(s0 + 2 * G_TILE_B);
            uint64_t dBl = mkdesc(s0 + 3 * G_TILE_B);
            #pragma unroll
            for (int ks = 0; ks < 4; ks++)
                mma_f16_ss(tmem, dAh + ks * 2, dBh + ks * 2, G_IDESC, (c != 0) || (ks != 0));
            #pragma unroll
            for (int ks = 0; ks < 4; ks++)
                mma_f16_ss(tmem, dAl + ks * 2, dBh + ks * 2, G_IDESC, 1u);
            #pragma unroll
            for (int ks = 0; ks < 4; ks++)
                mma_f16_ss(tmem, dAh + ks * 2, dBl + ks * 2, G_IDESC, 1u);
            TCGEN05_COMMIT(sb + 8 + b * 8);
        }
    }

    {
        const int b = (nc - 1) & 1;
        if (b == 0) { MBARRIER_WAIT_PARITY(sb + 8, pw0); }
        else        { MBARRIER_WAIT_PARITY(sb + 16, pw1); }
    }
    TCGEN05_FENCE_AFTER();
    __syncthreads();

    float* sepi = (float*)(smem + 1024);   // [128][65]
    const int ew = wid & 3;
    const int eh = wid >> 2;
    for (int rb = 0; rb < GTN; rb += 64) {
        uint32_t regs[32];
        TCGEN05_LD_32X32B_X32(regs, tmem + rb + eh * 32);
        TCGEN05_WAIT_LD();
        int srow = ew * 32 + lid;
        #pragma unroll
        for (int j = 0; j < 32; j++)
            sepi[srow * 65 + eh * 32 + j] = __uint_as_float(regs[j]);
        __syncthreads();
        int r0 = tid >> 4;
        int c4 = (tid & 15) << 2;
        int gcol = bx * GTN + rb + c4;
        float4 b4 = *(const float4*)(bias + gcol);
        #pragma unroll
        for (int p = 0; p < 8; p++) {
            int row = r0 + p * 16;
            float4 o;
            o.x = sepi[row * 65 + c4 + 0] + b4.x;
            o.y = sepi[row * 65 + c4 + 1] + b4.y;
            o.z = sepi[row * 65 + c4 + 2] + b4.z;
            o.w = sepi[row * 65 + c4 + 3] + b4.w;
            *(float4*)(C + (size_t)(by * GTM + row) * N + gcol) = o;
        }
        __syncthreads();
    }

    if (wid == 0) TCGEN05_DEALLOC(tmem, 128);

#else
    // ======== mma.sync fallback (128x128 tile, BK=32, cp.async pipeline) ========
    extern __shared__ char smem[];
    const int tid = threadIdx.x;
    const int wid = tid >> 5;
    const int lid = tid & 31;
    const int bx = blockIdx.x, by = blockIdx.y;
    const int wm = wid & 1;    // 2 warps along M (64 rows each)
    const int wn = wid >> 1;   // 4 warps along N (32 cols each)

    const int P = 40;                       // bf16 pitch (80B rows -> conflict-free ldmatrix)
    const int TILE_E = 128 * P;             // elems per tile
    const int STAGE_E = 4 * TILE_E;         // Ah, Al, Bh, Bl

    bf16* sbase = (bf16*)smem;

    const bf16* Agh = Ah + (size_t)(by * GTM) * K;
    const bf16* Agl = Al + (size_t)(by * GTM) * K;
    const bf16* Bgh = Bh + (size_t)(bx * GTN) * K;
    const bf16* Bgl = Bl + (size_t)(bx * GTN) * K;

    float acc[4][4][4];
    #pragma unroll
    for (int i = 0; i < 4; i++)
        #pragma unroll
        for (int j = 0; j < 4; j++)
            #pragma unroll
            for (int q = 0; q < 4; q++) acc[i][j][q] = 0.f;

    const int nc = K / 32;

    // issue cp.async loads of chunk c into stage s
    const int lr = tid >> 2;        // row 0..63 (x2 iterations covers 128)
    const int lseg = tid & 3;       // 8-bf16 segment within 32
    #define GF_ISSUE(c, s) do { \
        const int _kt = (c) * 32; \
        bf16* _st = sbase + (s) * STAGE_E; \
        _Pragma("unroll") \
        for (int _i = 0; _i < 2; _i++) { \
            int _r = lr + _i * 64; \
            uint32_t _d = smem_u32(_st + _r * P + lseg * 8); \
            cpa16(_d,                       Agh + (size_t)_r * K + _kt + lseg * 8); \
            cpa16(_d + TILE_E * 2,          Agl + (size_t)_r * K + _kt + lseg * 8); \
            cpa16(_d + 2 * TILE_E * 2,      Bgh + (size_t)_r * K + _kt + lseg * 8); \
            cpa16(_d + 3 * TILE_E * 2,      Bgl + (size_t)_r * K + _kt + lseg * 8); \
        } \
        CP_COMMIT(); \
    } while (0)

    GF_ISSUE(0, 0);

    // ldmatrix lane addressing
    const int a_row = lid & 15;          // + mf*16
    const int a_kh  = (lid >> 4) << 3;   // 0 or 8
    const int b_row = lid & 7;           // + nf*8
    const int b_kh  = ((lid >> 3) & 1) << 3;

    for (int c = 0; c < nc; c++) {
        const int s = c & 1;
        CP_WAIT0();
        __syncthreads();
        if (c + 1 < nc) GF_ISSUE(c + 1, s ^ 1);

        bf16* sAh = sbase + s * STAGE_E;
        bf16* sAl = sAh + TILE_E;
        bf16* sBh = sAl + TILE_E;
        bf16* sBl = sBh + TILE_E;

        #pragma unroll
        for (int ks = 0; ks < 2; ks++) {
            const int kc = ks * 16;
            uint32_t ah[4][4], al[4][4], bh[4][2], bl[4][2];
            #pragma unroll
            for (int mf = 0; mf < 4; mf++) {
                uint32_t addr = smem_u32(sAh + (wm * 64 + mf * 16 + a_row) * P + kc + a_kh);
                ldsm4(ah[mf][0], ah[mf][1], ah[mf][2], ah[mf][3], addr);
                uint32_t addr2 = smem_u32(sAl + (wm * 64 + mf * 16 + a_row) * P + kc + a_kh);
                ldsm4(al[mf][0], al[mf][1], al[mf][2], al[mf][3], addr2);
            }
            #pragma unroll
            for (int nf = 0; nf < 4; nf++) {
                uint32_t addr = smem_u32(sBh + (wn * 32 + nf * 8 + b_row) * P + kc + b_kh);
                ldsm2(bh[nf][0], bh[nf][1], addr);
                uint32_t addr2 = smem_u32(sBl + (wn * 32 + nf * 8 + b_row) * P + kc + b_kh);
                ldsm2(bl[nf][0], bl[nf][1], addr2);
            }
            #pragma unroll
            for (int mf = 0; mf < 4; mf++)
                #pragma unroll
                for (int nf = 0; nf < 4; nf++) {
                    mma16816(acc[mf][nf], ah[mf][0], ah[mf][1], ah[mf][2], ah[mf][3], bh[nf][0], bh[nf][1]);
                    mma16816(acc[mf][nf], al[mf][0], al[mf][1], al[mf][2], al[mf][3], bh[nf][0], bh[nf][1]);
                    mma16816(acc[mf][nf], ah[mf][0], ah[mf][1], ah[mf][2], ah[mf][3], bl[nf][0], bl[nf][1]);
                }
        }
    }

    // epilogue
    #pragma unroll
    for (int mf = 0; mf < 4; mf++) {
        #pragma unroll
        for (int nf = 0; nf < 4; nf++) {
            int row0 = by * GTM + wm * 64 + mf * 16 + (lid >> 2);
            int col  = bx * GTN + wn * 32 + nf * 8 + (lid & 3) * 2;
            float2 b2 = *(const float2*)(bias + col);
            float2 o0, o1;
            o0.x = acc[mf][nf][0] + b2.x;
            o0.y = acc[mf][nf][1] + b2.y;
            o1.x = acc[mf][nf][2] + b2.x;
            o1.y = acc[mf][nf][3] + b2.y;
            *(float2*)(C + (size_t)row0 * N + col) = o0;
            *(float2*)(C + (size_t)(row0 + 8) * N + col) = o1;
        }
    }
    #undef GF_ISSUE
#endif
}

// ---------------- flash attention: Br=128, Bc=64, 8x4 micro-tile ----------------
#define AP 68
#define ATTN2_SMEM ((128 + 64 + 64 + 128) * AP * 4)

__global__ __launch_bounds__(256) void attn2_kernel(
    const float* __restrict__ Q, const float* __restrict__ Kt,
    const float* __restrict__ V, const float* __restrict__ bias,
    bf16* __restrict__ Oh, bf16* __restrict__ Ol)
{
    extern __shared__ float sm[];
    float* Qs = sm;
    float* Ks = sm + 128 * AP;
    float* Vs = Ks + 64 * AP;
    float* Ps = Vs + 64 * AP;

    const int qt = blockIdx.x;
    const int bh = blockIdx.y;
    const int b = bh >> 4;
    const int h = bh & 15;
    const int qbase = qt * 128;
    const int tid = threadIdx.x;
    const int tx = tid & 15;
    const int ty = tid >> 4;

    const float* Qg = Q + ((size_t)(b * Sz + qbase)) * Hz + h * HDz;
    #pragma unroll
    for (int s = 0; s < 8; s++) {
        int f = s * 256 + tid;
        int row = f >> 4, c4 = (f & 15) << 2;
        *(float4*)&Qs[row * AP + c4] = *(const float4*)&Qg[(size_t)row * Hz + c4];
    }

    float m[8], l[8], o[8][4];
    #pragma unroll
    for (int i = 0; i < 8; i++) {
        m[i] = -1e30f; l[i] = 0.f;
        #pragma unroll
        for (int j = 0; j < 4; j++) o[i][j] = 0.f;
    }

    const float* biasrow = bias + ((size_t)h * BIAS_DIM + qbase) * BIAS_DIM;
    const float scale = 0.125f;

    for (int t = 0; t < Sz / 64; t++) {
        const int kbase = t * 64;
        __syncthreads();
        const float* Kg = Kt + ((size_t)(b * Sz + kbase)) * Hz + h * HDz;
        const float* Vg = V  + ((size_t)(b * Sz + kbase)) * Hz + h * HDz;
        #pragma unroll
        for (int s = 0; s < 4; s++) {
            int f = s * 256 + tid;
            int token = (f >> 2) & 63;
            int d = ((f & 3) | ((f >> 8) << 2)) << 2;
            float4 kv = *(const float4*)&Kg[(size_t)token * Hz + d];
            Ks[(d + 0) * AP + token] = kv.x;
            Ks[(d + 1) * AP + token] = kv.y;
            Ks[(d + 2) * AP + token] = kv.z;
            Ks[(d + 3) * AP + token] = kv.w;
            int row = f >> 4, c4 = (f & 15) << 2;
            *(float4*)&Vs[row * AP + c4] = *(const float4*)&Vg[(size_t)row * Hz + c4];
        }
        __syncthreads();

        float s_[8][4];
        #pragma unroll
        for (int i = 0; i < 8; i++)
            #pragma unroll
            for (int j = 0; j < 4; j++) s_[i][j] = 0.f;

        #pragma unroll 4
        for (int d = 0; d < 64; d++) {
            float bf[4];
            *(float4*)bf = *(const float4*)&Ks[d * AP + (tx << 2)];
            float af[8];
            #pragma unroll
            for (int i = 0; i < 8; i++) af[i] = Qs[(ty * 8 + i) * AP + d];
            #pragma unroll
            for (int i = 0; i < 8; i++) {
                s_[i][0] += af[i] * bf[0];
                s_[i][1] += af[i] * bf[1];
                s_[i][2] += af[i] * bf[2];
                s_[i][3] += af[i] * bf[3];
            }
        }

        #pragma unroll
        for (int i = 0; i < 8; i++) {
            const float* bp = biasrow + (size_t)(ty * 8 + i) * BIAS_DIM + kbase + (tx << 2);
            float sv0 = s_[i][0] * scale + __ldg(bp + 0);
            float sv1 = s_[i][1] * scale + __ldg(bp + 1);
            float sv2 = s_[i][2] * scale + __ldg(bp + 2);
            float sv3 = s_[i][3] * scale + __ldg(bp + 3);
            float rowm = fmaxf(fmaxf(sv0, sv1), fmaxf(sv2, sv3));
            rowm = fmaxf(rowm, __shfl_xor_sync(0xffffffffu, rowm, 1));
            rowm = fmaxf(rowm, __shfl_xor_sync(0xffffffffu, rowm, 2));
            rowm = fmaxf(rowm, __shfl_xor_sync(0xffffffffu, rowm, 4));
            rowm = fmaxf(rowm, __shfl_xor_sync(0xffffffffu, rowm, 8));
            float mnew = fmaxf(m[i], rowm);
            float corr = __expf(m[i] - mnew);
            m[i] = mnew;
            float p0 = __expf(sv0 - mnew);
            float p1 = __expf(sv1 - mnew);
            float p2 = __expf(sv2 - mnew);
            float p3 = __expf(sv3 - mnew);
            float rs = p0 + p1 + p2 + p3;
            rs += __shfl_xor_sync(0xffffffffu, rs, 1);
            rs += __shfl_xor_sync(0xffffffffu, rs, 2);
            rs += __shfl_xor_sync(0xffffffffu, rs, 4);
            rs += __shfl_xor_sync(0xffffffffu, rs, 8);
            l[i] = l[i] * corr + rs;
            o[i][0] *= corr; o[i][1] *= corr; o[i][2] *= corr; o[i][3] *= corr;
            float4 pv = make_float4(p0, p1, p2, p3);
            *(float4*)&Ps[(ty * 8 + i) * AP + (tx << 2)] = pv;
        }
        __syncthreads();

        #pragma unroll 4
        for (int kk = 0; kk < 64; kk++) {
            float bf[4];
            *(float4*)bf = *(const float4*)&Vs[kk * AP + (tx << 2)];
            float af[8];
            #pragma unroll
            for (int i = 0; i < 8; i++) af[i] = Ps[(ty * 8 + i) * AP + kk];
            #pragma unroll
            for (int i = 0; i < 8; i++) {
                o[i][0] += af[i] * bf[0];
                o[i][1] += af[i] * bf[1];
                o[i][2] += af[i] * bf[2];
                o[i][3] += af[i] * bf[3];
            }
        }
    }

    #pragma unroll
    for (int i = 0; i < 8; i++) {
        float inv = 1.f / l[i];
        size_t base = ((size_t)(b * Sz + qbase + ty * 8 + i)) * Hz + h * HDz + (tx << 2);
        #pragma unroll
        for (int j = 0; j < 4; j++) {
            float v = o[i][j] * inv;
            bf16 hh, ll;
            bsplit(v, hh, ll);
            Oh[base + j] = hh;
            Ol[base + j] = ll;
        }
    }
}

// ---------------- launch ----------------
extern "C" void kernel_launch(void* const* d_in, const int* in_sizes, int n_in,
                              void* d_out, int out_size)
{
    const float* hidden   = (const float*)d_in[0];
    const float* wpb      = (const float*)d_in[1];
    const float* pe_w     = (const float*)d_in[2];
    const float* pe_b     = (const float*)d_in[3];
    const float* pe_g     = (const float*)d_in[4];
    const float* pe_beta  = (const float*)d_in[5];
    const float* norm_g   = (const float*)d_in[6];
    const float* norm_b   = (const float*)d_in[7];
    const float* Wq = (const float*)d_in[8];  const float* bq = (const float*)d_in[9];
    const float* Wk = (const float*)d_in[10]; const float* bk = (const float*)d_in[11];
    const float* Wv = (const float*)d_in[12]; const float* bv = (const float*)d_in[13];
    const float* W1 = (const float*)d_in[14]; const float* b1 = (const float*)d_in[15];
    const float* g1 = (const float*)d_in[16]; const float* be1 = (const float*)d_in[17];
    const float* W2 = (const float*)d_in[18]; const float* b2 = (const float*)d_in[19];
    const float* g2 = (const float*)d_in[20]; const float* be2 = (const float*)d_in[21];
    const float* W3 = (const float*)d_in[22]; const float* b3 = (const float*)d_in[23];
    const float* g3 = (const float*)d_in[24]; const float* be3 = (const float*)d_in[25];
    const float* W4 = (const float*)d_in[26]; const float* b4 = (const float*)d_in[27];
    float* out = (float*)d_out;

    cudaFuncSetAttribute(attn2_kernel, cudaFuncAttributeMaxDynamicSharedMemorySize, ATTN2_SMEM);
    cudaFuncSetAttribute(gemm_tc, cudaFuncAttributeMaxDynamicSharedMemorySize, GEMM_SMEM);

    float* d_pe  = nullptr; cudaGetSymbolAddress((void**)&d_pe,  g_pe);
    float* d_q   = nullptr; cudaGetSymbolAddress((void**)&d_q,   g_q);
    float* d_k   = nullptr; cudaGetSymbolAddress((void**)&d_k,   g_k);
    float* d_v   = nullptr; cudaGetSymbolAddress((void**)&d_v,   g_v);
    float* d_ta  = nullptr; cudaGetSymbolAddress((void**)&d_ta,  g_ta);
    bf16* d_xh = nullptr;  cudaGetSymbolAddress((void**)&d_xh,  g_xh);
    bf16* d_xl = nullptr;  cudaGetSymbolAddress((void**)&d_xl,  g_xl);
    bf16* d_cth = nullptr; cudaGetSymbolAddress((void**)&d_cth, g_cth);
    bf16* d_ctl = nullptr; cudaGetSymbolAddress((void**)&d_ctl, g_ctl);
    bf16* d_tah = nullptr; cudaGetSymbolAddress((void**)&d_tah, g_tah);
    bf16* d_tal = nullptr; cudaGetSymbolAddress((void**)&d_tal, g_tal);
    bf16 *d_wqh, *d_wql, *d_wkh, *d_wkl, *d_wvh, *d_wvl;
    bf16 *d_w1h, *d_w1l, *d_w2h, *d_w2l, *d_w3h, *d_w3l, *d_w4h, *d_w4l;
    cudaGetSymbolAddress((void**)&d_wqh, g_wqh); cudaGetSymbolAddress((void**)&d_wql, g_wql);
    cudaGetSymbolAddress((void**)&d_wkh, g_wkh); cudaGetSymbolAddress((void**)&d_wkl, g_wkl);
    cudaGetSymbolAddress((void**)&d_wvh, g_wvh); cudaGetSymbolAddress((void**)&d_wvl, g_wvl);
    cudaGetSymbolAddress((void**)&d_w1h, g_w1h); cudaGetSymbolAddress((void**)&d_w1l, g_w1l);
    cudaGetSymbolAddress((void**)&d_w2h, g_w2h); cudaGetSymbolAddress((void**)&d_w2l, g_w2l);
    cudaGetSymbolAddress((void**)&d_w3h, g_w3h); cudaGetSymbolAddress((void**)&d_w3l, g_w3l);
    cudaGetSymbolAddress((void**)&d_w4h, g_w4h); cudaGetSymbolAddress((void**)&d_w4l, g_w4l);

    const int M = Bz * Sz;  // 4096

    // weight prep: W[K][N] -> T[N][K] split
    wsplit_kernel<<<dim3(32, 32), 256>>>(Wq, d_wqh, d_wql, 1024, 1024);
    wsplit_kernel<<<dim3(32, 32), 256>>>(Wk, d_wkh, d_wkl, 1024, 1024);
    wsplit_kernel<<<dim3(32, 32), 256>>>(Wv, d_wvh, d_wvl, 1024, 1024);
    wsplit_kernel<<<dim3(64, 32), 256>>>(W1, d_w1h, d_w1l, 1024, 2048);
    wsplit_kernel<<<dim3(64, 64), 256>>>(W2, d_w2h, d_w2l, 2048, 2048);
    wsplit_kernel<<<dim3(64, 64), 256>>>(W3, d_w3h, d_w3l, 2048, 2048);
    wsplit_kernel<<<dim3(32, 64), 256>>>(W4, d_w4h, d_w4l, 2048, 1024);

    pe_kernel<<<Sz, 256>>>(pe_w, pe_b, pe_g, pe_beta, d_pe);
    x_kernel<<<M, 256>>>(hidden, d_pe, norm_g, norm_b, d_xh, d_xl);

    // QKV projections (tensor cores)
    gemm_tc<<<dim3(8, 32), 256, GEMM_SMEM>>>(d_xh, d_xl, d_wqh, d_wql, bq, d_q, M, 1024, 1024);
    gemm_tc<<<dim3(8, 32), 256, GEMM_SMEM>>>(d_xh, d_xl, d_wkh, d_wkl, bk, d_k, M, 1024, 1024);
    gemm_tc<<<dim3(8, 32), 256, GEMM_SMEM>>>(d_xh, d_xl, d_wvh, d_wvl, bv, d_v, M, 1024, 1024);

    // attention
    attn2_kernel<<<dim3(Sz / 128, Bz * NHz), 256, ATTN2_SMEM>>>(d_q, d_k, d_v, wpb, d_cth, d_ctl);

    // MLP head
    gemm_tc<<<dim3(16, 32), 256, GEMM_SMEM>>>(d_cth, d_ctl, d_w1h, d_w1l, b1, d_ta, M, 2048, 1024);
    ln_split_kernel<<<M, 256>>>(d_ta, d_tah, d_tal, g1, be1, 2048);
    gemm_tc<<<dim3(16, 32), 256, GEMM_SMEM>>>(d_tah, d_tal, d_w2h, d_w2l, b2, d_ta, M, 2048, 2048);
    ln_split_kernel<<<M, 256>>>(d_ta, d_tah, d_tal, g2, be2, 2048);
    gemm_tc<<<dim3(16, 32), 256, GEMM_SMEM>>>(d_tah, d_tal, d_w3h, d_w3l, b3, d_ta, M, 2048, 2048);
    ln_split_kernel<<<M, 256>>>(d_ta, d_tah, d_tal, g3, be3, 2048);
    gemm_tc<<<dim3(8, 32), 256, GEMM_SMEM>>>(d_tah, d_tal, d_w4h, d_w4l, b4, out, M, 1024, 2048);
}